// round 2
// baseline (speedup 1.0000x reference)
#include <cuda_runtime.h>
#include <math.h>

typedef unsigned long long ull;

__device__ __forceinline__ ull fma2(ull a, ull b, ull c) {
    ull d;
    asm("fma.rn.f32x2 %0, %1, %2, %3;" : "=l"(d) : "l"(a), "l"(b), "l"(c));
    return d;
}
__device__ __forceinline__ ull mul2(ull a, ull b) {
    ull d;
    asm("mul.rn.f32x2 %0, %1, %2;" : "=l"(d) : "l"(a), "l"(b));
    return d;
}
__device__ __forceinline__ ull pack2(float x, float y) {
    ull r;
    asm("mov.b64 %0, {%1, %2};" : "=l"(r) : "f"(x), "f"(y));
    return r;
}
__device__ __forceinline__ float2 unpack2(ull a) {
    float2 r;
    asm("mov.b64 {%0, %1}, %2;" : "=f"(r.x), "=f"(r.y) : "l"(a));
    return r;
}

static constexpr int Bq = 8;
static constexpr int Cc = 64;
static constexpr int Nn = 4096;
static constexpr int TQ = 64;
static constexpr int TK = 64;
static constexpr int NTHREADS = 256;

// smem layout (float offsets)
static constexpr int OFF_QSD = 0;                 // Qsd[c][2r+e]  : [64][128]
static constexpr int OFF_KS  = 64 * 128;          // Ks [c][m]     : [64][68]
static constexpr int OFF_KT  = OFF_KS + 64 * 68;  // KT [m][c]     : [64][68]
static constexpr int OFF_PSD = OFF_KT + 64 * 68;  // Psd[m][2r+e]  : [64][128] (XOR-swizzled granules)
static constexpr int SMEM_FLOATS = OFF_PSD + 64 * 128;  // 25088 floats = 100352 B

__global__ void __launch_bounds__(NTHREADS, 2)
attn_f32x2_kernel(const float* __restrict__ x, float* __restrict__ out) {
    extern __shared__ float sm[];
    float* Qsd = sm + OFF_QSD;
    float* Ks  = sm + OFF_KS;
    float* KT  = sm + OFF_KT;
    float* Psd = sm + OFF_PSD;

    const int b  = blockIdx.x >> 6;         // 64 q-tiles per batch
    const int q0 = (blockIdx.x & 63) * TQ;
    const float* f = x + (size_t)b * Cc * Nn;

    const int tid = threadIdx.x;
    const int ty  = tid >> 4;   // 0..15 -> rows r0 = 4*ty
    const int tx  = tid & 15;   // 0..15 -> cols m0 = 4*tx / channels c0 = 4*tx

    // ---- Load Q tile, duplicated pairs: Qsd[c][2r] = Qsd[c][2r+1] = f[c][q0+r]
    #pragma unroll 4
    for (int i = tid; i < 64 * 16; i += NTHREADS) {
        const int c = i >> 4;
        const int g = (i & 15) * 4;  // rows g..g+3
        const float4 v = *reinterpret_cast<const float4*>(f + c * Nn + q0 + g);
        ull* dst = reinterpret_cast<ull*>(Qsd + c * 128 + 2 * g);
        dst[0] = pack2(v.x, v.x);
        dst[1] = pack2(v.y, v.y);
        dst[2] = pack2(v.z, v.z);
        dst[3] = pack2(v.w, v.w);
    }

    float mi[4], li[4];
    #pragma unroll
    for (int i = 0; i < 4; i++) { mi[i] = -INFINITY; li[i] = 0.0f; }

    // O accumulators: o2[row][chpair], channels c0..c0+3 as 2 packed pairs
    ull o2[4][2];
    #pragma unroll
    for (int i = 0; i < 4; i++) { o2[i][0] = 0ull; o2[i][1] = 0ull; }

    #pragma unroll 1
    for (int kt = 0; kt < Nn / TK; kt++) {
        const int k0 = kt * TK;

        __syncthreads();  // previous PV reads finished before overwriting tiles

        // ---- Load K/V tile (same data): Ks[c][m], KT[m][c]
        #pragma unroll 4
        for (int i = tid; i < 64 * 16; i += NTHREADS) {
            const int c = i >> 4;
            const int m = (i & 15) * 4;
            const float4 v = *reinterpret_cast<const float4*>(f + c * Nn + k0 + m);
            *reinterpret_cast<float4*>(Ks + c * 68 + m) = v;
            KT[(m + 0) * 68 + c] = v.x;
            KT[(m + 1) * 68 + c] = v.y;
            KT[(m + 2) * 68 + c] = v.z;
            KT[(m + 3) * 68 + c] = v.w;
        }
        __syncthreads();

        // ---- S = Q^T K : s2[row][mpair], packed over m
        ull s2[4][2];
        #pragma unroll
        for (int i = 0; i < 4; i++) { s2[i][0] = 0ull; s2[i][1] = 0ull; }

        #pragma unroll 16
        for (int c = 0; c < 64; c++) {
            const ulonglong2 qa = *reinterpret_cast<const ulonglong2*>(Qsd + c * 128 + 8 * ty);
            const ulonglong2 qb = *reinterpret_cast<const ulonglong2*>(Qsd + c * 128 + 8 * ty + 4);
            const ulonglong2 kv = *reinterpret_cast<const ulonglong2*>(Ks + c * 68 + 4 * tx);
            s2[0][0] = fma2(qa.x, kv.x, s2[0][0]);
            s2[0][1] = fma2(qa.x, kv.y, s2[0][1]);
            s2[1][0] = fma2(qa.y, kv.x, s2[1][0]);
            s2[1][1] = fma2(qa.y, kv.y, s2[1][1]);
            s2[2][0] = fma2(qb.x, kv.x, s2[2][0]);
            s2[2][1] = fma2(qb.x, kv.y, s2[2][1]);
            s2[3][0] = fma2(qb.y, kv.x, s2[3][0]);
            s2[3][1] = fma2(qb.y, kv.y, s2[3][1]);
        }

        // ---- Online softmax (rows owned by the 16 tx-lanes of each half-warp)
        float p[4][4];
        #pragma unroll
        for (int i = 0; i < 4; i++) {
            const float2 a = unpack2(s2[i][0]);
            const float2 c2 = unpack2(s2[i][1]);
            float tmax = fmaxf(fmaxf(a.x, a.y), fmaxf(c2.x, c2.y));
            #pragma unroll
            for (int off = 1; off < 16; off <<= 1)
                tmax = fmaxf(tmax, __shfl_xor_sync(0xffffffffu, tmax, off));
            const float mnew = fmaxf(mi[i], tmax);
            const float scale = __expf(mi[i] - mnew);
            p[i][0] = __expf(a.x - mnew);
            p[i][1] = __expf(a.y - mnew);
            p[i][2] = __expf(c2.x - mnew);
            p[i][3] = __expf(c2.y - mnew);
            float rs = (p[i][0] + p[i][1]) + (p[i][2] + p[i][3]);
            #pragma unroll
            for (int off = 1; off < 16; off <<= 1)
                rs += __shfl_xor_sync(0xffffffffu, rs, off);
            li[i] = li[i] * scale + rs;
            mi[i] = mnew;
            const ull sc2 = pack2(scale, scale);
            o2[i][0] = mul2(o2[i][0], sc2);
            o2[i][1] = mul2(o2[i][1], sc2);
        }

        // ---- Store P duplicated: Psd[m][2r+e], XOR-swizzled 16B granules.
        // granule g holds rows 2g,2g+1; swizzle g' = g ^ (m & 31)
        #pragma unroll
        for (int j = 0; j < 4; j++) {
            const int m = 4 * tx + j;
            const int sw = m & 31;
            ulonglong2 d01, d23;
            d01.x = pack2(p[0][j], p[0][j]);
            d01.y = pack2(p[1][j], p[1][j]);
            d23.x = pack2(p[2][j], p[2][j]);
            d23.y = pack2(p[3][j], p[3][j]);
            *reinterpret_cast<ulonglong2*>(Psd + m * 128 + (((2 * ty + 0) ^ sw) << 2)) = d01;
            *reinterpret_cast<ulonglong2*>(Psd + m * 128 + (((2 * ty + 1) ^ sw) << 2)) = d23;
        }
        __syncthreads();

        // ---- O += P * V : packed over channels, P broadcast (pre-duplicated)
        #pragma unroll 16
        for (int m = 0; m < 64; m++) {
            const int sw = m & 31;
            const float* prow = Psd + m * 128;
            const ulonglong2 pa = *reinterpret_cast<const ulonglong2*>(prow + (((2 * ty + 0) ^ sw) << 2));
            const ulonglong2 pb = *reinterpret_cast<const ulonglong2*>(prow + (((2 * ty + 1) ^ sw) << 2));
            const ulonglong2 vv = *reinterpret_cast<const ulonglong2*>(KT + m * 68 + 4 * tx);
            o2[0][0] = fma2(pa.x, vv.x, o2[0][0]);
            o2[0][1] = fma2(pa.x, vv.y, o2[0][1]);
            o2[1][0] = fma2(pa.y, vv.x, o2[1][0]);
            o2[1][1] = fma2(pa.y, vv.y, o2[1][1]);
            o2[2][0] = fma2(pb.x, vv.x, o2[2][0]);
            o2[2][1] = fma2(pb.x, vv.y, o2[2][1]);
            o2[3][0] = fma2(pb.y, vv.x, o2[3][0]);
            o2[3][1] = fma2(pb.y, vv.y, o2[3][1]);
        }
    }

    // ---- Epilogue: out[b][c][n] = x[b][c][n] + O[r][c] / l[r]
    const float* xb = x + (size_t)b * Cc * Nn;
    float* ob = out + (size_t)b * Cc * Nn;
    #pragma unroll
    for (int i = 0; i < 4; i++) {
        const float inv = 1.0f / li[i];
        const int n = q0 + 4 * ty + i;
        const float2 oA = unpack2(o2[i][0]);
        const float2 oB = unpack2(o2[i][1]);
        const int c0 = 4 * tx;
        ob[(c0 + 0) * Nn + n] = xb[(c0 + 0) * Nn + n] + oA.x * inv;
        ob[(c0 + 1) * Nn + n] = xb[(c0 + 1) * Nn + n] + oA.y * inv;
        ob[(c0 + 2) * Nn + n] = xb[(c0 + 2) * Nn + n] + oB.x * inv;
        ob[(c0 + 3) * Nn + n] = xb[(c0 + 3) * Nn + n] + oB.y * inv;
    }
}

extern "C" void kernel_launch(void* const* d_in, const int* in_sizes, int n_in,
                              void* d_out, int out_size) {
    const float* x = (const float*)d_in[0];
    float* out = (float*)d_out;
    (void)in_sizes; (void)n_in; (void)out_size;

    static bool attr_set = false;
    if (!attr_set) {
        cudaFuncSetAttribute(attn_f32x2_kernel,
                             cudaFuncAttributeMaxDynamicSharedMemorySize,
                             SMEM_FLOATS * (int)sizeof(float));
        attr_set = true;
    }

    const int grid = Bq * (Nn / TQ);  // 512 CTAs
    attn_f32x2_kernel<<<grid, NTHREADS, SMEM_FLOATS * sizeof(float)>>>(x, out);
}

// round 4
// speedup vs baseline: 4.1666x; 4.1666x over previous
#include <cuda_runtime.h>
#include <cuda_bf16.h>
#include <math.h>
#include <stdint.h>

static constexpr int Bq = 8, Cc = 64, Nn = 4096, TQ = 128, TK = 128, NT = 256;
static constexpr long CN = (long)Cc * Nn;
static constexpr float LOG2E = 1.4426950408889634f;

// smem byte offsets
static constexpr int OFF_FS  = 0;                    // fp32 staging [64][132] = 33792 B
static constexpr int OFF_KHI = 33792;                // KT[pos 128][chan 64] bf16 swizzled, 16KB
static constexpr int OFF_KLO = OFF_KHI + 16384;
static constexpr int OFF_VHI = OFF_KLO + 16384;      // VT[chan 64][pos 128] bf16 swizzled, 16KB
static constexpr int OFF_VLO = OFF_VHI + 16384;
static constexpr int SMEM_TOTAL = OFF_VLO + 16384;   // 99328 B

__device__ float    g_norm[Bq * Nn];
__device__ unsigned g_mmax[Bq];

// ---------------- helpers ----------------
__device__ __forceinline__ float ex2a(float x) {
    float y;
    asm("ex2.approx.f32 %0, %1;" : "=f"(y) : "f"(x));
    return y;
}
// pack: low half <- e0, high half <- e1
__device__ __forceinline__ uint32_t cvt2(float e1_hi, float e0_lo) {
    uint32_t r;
    asm("cvt.rn.bf16x2.f32 %0, %1, %2;" : "=r"(r) : "f"(e1_hi), "f"(e0_lo));
    return r;
}
// split (e0,e1) fp32 pair -> packed bf16x2 hi + packed bf16x2 lo
__device__ __forceinline__ void split_pair(float e0, float e1, uint32_t& h, uint32_t& l) {
    h = cvt2(e1, e0);
    const float h0 = __uint_as_float(h << 16);
    const float h1 = __uint_as_float(h & 0xFFFF0000u);
    l = cvt2(e1 - h1, e0 - h0);
}
__device__ __forceinline__ void mma16816(float* d, const uint32_t* a, const uint32_t* b) {
    asm volatile(
        "mma.sync.aligned.m16n8k16.row.col.f32.bf16.bf16.f32 "
        "{%0,%1,%2,%3}, {%4,%5,%6,%7}, {%8,%9}, {%0,%1,%2,%3};"
        : "+f"(d[0]), "+f"(d[1]), "+f"(d[2]), "+f"(d[3])
        : "r"(a[0]), "r"(a[1]), "r"(a[2]), "r"(a[3]), "r"(b[0]), "r"(b[1]));
}

// Load f[:, k0:k0+128] -> Fs fp32 staging + VT hi/lo (natural layout, swizzled)
__device__ __forceinline__ void load_tile(const float* __restrict__ f, int k0,
                                          char* sm, int tid) {
    float* Fs = (float*)(sm + OFF_FS);
    const int l = tid & 31;
    const int mv = l * 4;
    const uint32_t vgran = (uint32_t)(l >> 1);        // (2*mv)>>4
    const uint32_t voff8 = (uint32_t)((2 * mv) & 15); // 0 or 8
    int c = tid >> 5;
    #pragma unroll
    for (int it = 0; it < 8; it++, c += 8) {
        const float4 v = *reinterpret_cast<const float4*>(f + (size_t)c * Nn + k0 + mv);
        *reinterpret_cast<float4*>(Fs + c * 132 + mv) = v;
        uint32_t h0, l0, h1, l1;
        split_pair(v.x, v.y, h0, l0);
        split_pair(v.z, v.w, h1, l1);
        const uint32_t go = (uint32_t)c * 256 + (((vgran ^ ((uint32_t)c & 15u)) << 4) | voff8);
        *reinterpret_cast<uint2*>(sm + OFF_VHI + go) = make_uint2(h0, h1);
        *reinterpret_cast<uint2*>(sm + OFF_VLO + go) = make_uint2(l0, l1);
    }
}

// Fs -> KT[pos][chan] hi/lo bf16, rows 128B, granule XOR (pos&7)
__device__ __forceinline__ void transpose_split(char* sm, int tid) {
    const float* Fs = (const float*)(sm + OFF_FS);
    const int pos = tid >> 1, c0 = (tid & 1) * 32;
    const uint32_t pg = (uint32_t)(pos & 7);
    uint32_t hi[16], lo[16];
    #pragma unroll
    for (int j = 0; j < 16; j++) {
        const float a = Fs[(c0 + 2 * j) * 132 + pos];
        const float b = Fs[(c0 + 2 * j + 1) * 132 + pos];
        split_pair(a, b, hi[j], lo[j]);
    }
    const uint32_t rowb = (uint32_t)pos * 128;
    #pragma unroll
    for (int gg = 0; gg < 4; gg++) {
        const uint32_t off = rowb + ((((uint32_t)(c0 >> 3) + gg) ^ pg) << 4);
        *reinterpret_cast<uint4*>(sm + OFF_KHI + off) =
            make_uint4(hi[4 * gg], hi[4 * gg + 1], hi[4 * gg + 2], hi[4 * gg + 3]);
        *reinterpret_cast<uint4*>(sm + OFF_KLO + off) =
            make_uint4(lo[4 * gg], lo[4 * gg + 1], lo[4 * gg + 2], lo[4 * gg + 3]);
    }
}

// ---------------- pre-pass ----------------
__global__ void init_mmax_kernel() {
    if (threadIdx.x < Bq) g_mmax[threadIdx.x] = 0u;
}
__global__ void norms_kernel(const float* __restrict__ x) {
    __shared__ float red[128];
    const int b = blockIdx.x >> 5;
    const int n = (blockIdx.x & 31) * 128 + threadIdx.x;
    float s = 0.0f;
    #pragma unroll 8
    for (int c = 0; c < Cc; c++) {
        const float v = x[(size_t)b * CN + (size_t)c * Nn + n];
        s += v * v;
    }
    const float nr = sqrtf(s);
    g_norm[b * Nn + n] = nr;
    red[threadIdx.x] = nr;
    __syncthreads();
    for (int st = 64; st > 0; st >>= 1) {
        if (threadIdx.x < st) red[threadIdx.x] = fmaxf(red[threadIdx.x], red[threadIdx.x + st]);
        __syncthreads();
    }
    if (threadIdx.x == 0) atomicMax(&g_mmax[b], __float_as_uint(red[0]));
}

// ---------------- main kernel ----------------
__global__ void __launch_bounds__(NT, 2)
attn_hmma_kernel(const float* __restrict__ x, float* __restrict__ out) {
    extern __shared__ char sm[];
    const int tid = threadIdx.x, w = tid >> 5, lane = tid & 31;
    const int g = lane >> 2, t = lane & 3;
    const int b = blockIdx.x >> 5, q0 = (blockIdx.x & 31) * TQ;
    const float* f = x + (size_t)b * CN;

    // rows this thread owns: qr, qr+8
    const int qr = 16 * w + g;
    const float mmax = __uint_as_float(g_mmax[b]);
    const float nZL0 = -(g_norm[b * Nn + q0 + qr] * mmax) * LOG2E;
    const float nZL1 = -(g_norm[b * Nn + q0 + qr + 8] * mmax) * LOG2E;

    // ---- prologue: build Q tile in KT buffers, extract A-fragments
    load_tile(f, q0, sm, tid);
    __syncthreads();
    transpose_split(sm, tid);
    __syncthreads();

    uint32_t qh[4][4], ql[4][4];
    {
        const uint32_t r0 = (uint32_t)qr * 128 + 4 * t;
        const uint32_t r8 = r0 + 8 * 128;
        const uint32_t pgq = (uint32_t)(qr & 7);
        #pragma unroll
        for (int kc = 0; kc < 4; kc++) {
            const uint32_t g0 = (((uint32_t)(2 * kc) ^ pgq) << 4);
            const uint32_t g1 = (((uint32_t)(2 * kc + 1) ^ pgq) << 4);
            qh[kc][0] = *(const uint32_t*)(sm + OFF_KHI + r0 + g0);
            qh[kc][1] = *(const uint32_t*)(sm + OFF_KHI + r8 + g0);
            qh[kc][2] = *(const uint32_t*)(sm + OFF_KHI + r0 + g1);
            qh[kc][3] = *(const uint32_t*)(sm + OFF_KHI + r8 + g1);
            ql[kc][0] = *(const uint32_t*)(sm + OFF_KLO + r0 + g0);
            ql[kc][1] = *(const uint32_t*)(sm + OFF_KLO + r8 + g0);
            ql[kc][2] = *(const uint32_t*)(sm + OFF_KLO + r0 + g1);
            ql[kc][3] = *(const uint32_t*)(sm + OFF_KLO + r8 + g1);
        }
    }

    float O[8][4];
    #pragma unroll
    for (int i = 0; i < 8; i++)
        #pragma unroll
        for (int j = 0; j < 4; j++) O[i][j] = 0.0f;
    float lac0 = 0.0f, lac1 = 0.0f;

    #pragma unroll 1
    for (int kt = 0; kt < Nn / TK; kt++) {
        __syncthreads();  // previous compute done reading KT/VT
        load_tile(f, kt * TK, sm, tid);
        __syncthreads();
        transpose_split(sm, tid);
        __syncthreads();

        #pragma unroll 1
        for (int pc = 0; pc < 8; pc++) {
            // ---- S fragments for ntiles 2pc, 2pc+1 (3-pass bf16)
            float sa[2][4];
            #pragma unroll
            for (int u = 0; u < 2; u++) {
                const int pos = 8 * (2 * pc + u) + g;
                const uint32_t rb = (uint32_t)pos * 128 + 4 * t;
                const uint32_t pg = (uint32_t)(pos & 7);
                float* acc = sa[u];
                acc[0] = acc[1] = acc[2] = acc[3] = 0.0f;
                #pragma unroll
                for (int kc = 0; kc < 4; kc++) {
                    const uint32_t o0 = rb + (((uint32_t)(2 * kc) ^ pg) << 4);
                    const uint32_t o1 = rb + (((uint32_t)(2 * kc + 1) ^ pg) << 4);
                    uint32_t bh[2], bl[2];
                    bh[0] = *(const uint32_t*)(sm + OFF_KHI + o0);
                    bh[1] = *(const uint32_t*)(sm + OFF_KHI + o1);
                    bl[0] = *(const uint32_t*)(sm + OFF_KLO + o0);
                    bl[1] = *(const uint32_t*)(sm + OFF_KLO + o1);
                    mma16816(acc, qh[kc], bh);
                    mma16816(acc, ql[kc], bh);
                    mma16816(acc, qh[kc], bl);
                }
            }
            // ---- exp (Z-bound, no rescale) + l accumulation
            float p[2][4];
            #pragma unroll
            for (int u = 0; u < 2; u++) {
                p[u][0] = ex2a(fmaf(sa[u][0], LOG2E, nZL0));
                p[u][1] = ex2a(fmaf(sa[u][1], LOG2E, nZL0));
                p[u][2] = ex2a(fmaf(sa[u][2], LOG2E, nZL1));
                p[u][3] = ex2a(fmaf(sa[u][3], LOG2E, nZL1));
                lac0 += p[u][0] + p[u][1];
                lac1 += p[u][2] + p[u][3];
            }
            // ---- pack P as PV A-fragment (register-only)
            uint32_t pah[4], pal[4];
            split_pair(p[0][0], p[0][1], pah[0], pal[0]);
            split_pair(p[0][2], p[0][3], pah[1], pal[1]);
            split_pair(p[1][0], p[1][1], pah[2], pal[2]);
            split_pair(p[1][2], p[1][3], pah[3], pal[3]);
            // ---- PV: O += Phi*Vhi + Plo*Vhi + Phi*Vlo
            #pragma unroll
            for (int ntv = 0; ntv < 8; ntv++) {
                const uint32_t chan = 8 * ntv + g;
                const uint32_t rbv = chan * 256 + 4 * t;
                const uint32_t cg = chan & 15;
                const uint32_t o0 = rbv + (((uint32_t)(2 * pc) ^ cg) << 4);
                const uint32_t o1 = rbv + (((uint32_t)(2 * pc + 1) ^ cg) << 4);
                uint32_t bh[2], bl[2];
                bh[0] = *(const uint32_t*)(sm + OFF_VHI + o0);
                bh[1] = *(const uint32_t*)(sm + OFF_VHI + o1);
                bl[0] = *(const uint32_t*)(sm + OFF_VLO + o0);
                bl[1] = *(const uint32_t*)(sm + OFF_VLO + o1);
                mma16816(O[ntv], pah, bh);
                mma16816(O[ntv], pal, bh);
                mma16816(O[ntv], pah, bl);
            }
        }
    }

    // ---- reduce l across the 4 t-lanes sharing each row
    lac0 += __shfl_xor_sync(0xffffffffu, lac0, 1);
    lac0 += __shfl_xor_sync(0xffffffffu, lac0, 2);
    lac1 += __shfl_xor_sync(0xffffffffu, lac1, 1);
    lac1 += __shfl_xor_sync(0xffffffffu, lac1, 2);
    const float li0 = 1.0f / lac0;
    const float li1 = 1.0f / lac1;

    // ---- epilogue: out = x + O / l
    const int n0 = q0 + qr;
    const int n1 = n0 + 8;
    #pragma unroll
    for (int ntv = 0; ntv < 8; ntv++) {
        const int c = 8 * ntv + 2 * t;
        const size_t i00 = (size_t)b * CN + (size_t)c * Nn;
        out[i00 + n0]       = x[i00 + n0]       + O[ntv][0] * li0;
        out[i00 + Nn + n0]  = x[i00 + Nn + n0]  + O[ntv][1] * li0;
        out[i00 + n1]       = x[i00 + n1]       + O[ntv][2] * li1;
        out[i00 + Nn + n1]  = x[i00 + Nn + n1]  + O[ntv][3] * li1;
    }
}

extern "C" void kernel_launch(void* const* d_in, const int* in_sizes, int n_in,
                              void* d_out, int out_size) {
    const float* x = (const float*)d_in[0];
    float* out = (float*)d_out;
    (void)in_sizes; (void)n_in; (void)out_size;

    cudaFuncSetAttribute(attn_hmma_kernel,
                         cudaFuncAttributeMaxDynamicSharedMemorySize, SMEM_TOTAL);

    init_mmax_kernel<<<1, 32>>>();
    norms_kernel<<<Bq * 32, 128>>>(x);
    attn_hmma_kernel<<<Bq * 32, NT, SMEM_TOTAL>>>(x, out);
}

// round 7
// speedup vs baseline: 4.9288x; 1.1829x over previous
#include <cuda_runtime.h>
#include <cuda_bf16.h>
#include <math.h>
#include <stdint.h>

static constexpr int Bq = 8, Cc = 64, Nn = 4096, TQ = 256, TK = 128, NT = 512;
static constexpr long CN = (long)Cc * Nn;
static constexpr float LOG2E = 1.4426950408889634f;

// ---- persistent converted operands (bf16 hi/lo, swizzle baked in)
__device__ char g_kth[(size_t)Bq * Nn * 128];     // KT[b][pos][chan] hi: 128B rows
__device__ char g_ktl[(size_t)Bq * Nn * 128];
__device__ char g_vh [(size_t)Bq * 32 * 16384];   // V[b][kt][chan][pos-in-tile] hi
__device__ char g_vl [(size_t)Bq * 32 * 16384];
__device__ float    g_norm[Bq * Nn];
__device__ unsigned g_mmax[Bq];

// ---- convert-kernel smem layout (bytes)
static constexpr int OFF_FS  = 0;                 // fp32 staging [64][132]
static constexpr int OFF_KHI = 33792;
static constexpr int OFF_KLO = OFF_KHI + 16384;
static constexpr int OFF_VHI = OFF_KLO + 16384;
static constexpr int OFF_VLO = OFF_VHI + 16384;
static constexpr int CONV_SMEM = OFF_VLO + 16384; // 99328 B

// ---- main-kernel smem: 2 x 64KB buffers {KHI,KLO,VHI,VLO}
static constexpr int BUF_BYTES = 65536;
static constexpr int MAIN_SMEM = 2 * BUF_BYTES;   // 131072 B

// ---------------- helpers ----------------
__device__ __forceinline__ float ex2a(float x) {
    float y;
    asm("ex2.approx.f32 %0, %1;" : "=f"(y) : "f"(x));
    return y;
}
__device__ __forceinline__ uint32_t cvt2(float e1_hi, float e0_lo) {
    uint32_t r;
    asm("cvt.rn.bf16x2.f32 %0, %1, %2;" : "=r"(r) : "f"(e1_hi), "f"(e0_lo));
    return r;
}
__device__ __forceinline__ void split_pair(float e0, float e1, uint32_t& h, uint32_t& l) {
    h = cvt2(e1, e0);
    const float h0 = __uint_as_float(h << 16);
    const float h1 = __uint_as_float(h & 0xFFFF0000u);
    l = cvt2(e1 - h1, e0 - h0);
}
__device__ __forceinline__ void mma16816(float* d, const uint32_t* a, const uint32_t* b) {
    asm volatile(
        "mma.sync.aligned.m16n8k16.row.col.f32.bf16.bf16.f32 "
        "{%0,%1,%2,%3}, {%4,%5,%6,%7}, {%8,%9}, {%0,%1,%2,%3};"
        : "+f"(d[0]), "+f"(d[1]), "+f"(d[2]), "+f"(d[3])
        : "r"(a[0]), "r"(a[1]), "r"(a[2]), "r"(a[3]), "r"(b[0]), "r"(b[1]));
}
__device__ __forceinline__ uint32_t smem_u32(const void* p) {
    uint32_t a;
    asm("{ .reg .u64 t; cvta.to.shared.u64 t, %1; cvt.u32.u64 %0, t; }" : "=r"(a) : "l"(p));
    return a;
}
#define CP_ASYNC16(dst, src) \
    asm volatile("cp.async.cg.shared.global [%0], [%1], 16;" :: "r"(dst), "l"(src) : "memory")
#define CP_COMMIT() asm volatile("cp.async.commit_group;" ::: "memory")
#define CP_WAIT1()  asm volatile("cp.async.wait_group 1;" ::: "memory")
#define CP_WAIT0()  asm volatile("cp.async.wait_group 0;" ::: "memory")

// ---------------- pre-pass ----------------
__global__ void init_mmax_kernel() {
    if (threadIdx.x < Bq) g_mmax[threadIdx.x] = 0u;
}

// Per (b, kt): load fp32 tile, split to bf16 hi/lo (V natural + K transposed),
// bake swizzle, compute per-position norms, write converted tiles to global.
__global__ void __launch_bounds__(256)
convert_kernel(const float* __restrict__ x) {
    extern __shared__ char sm[];
    const int tid = threadIdx.x;
    const int b = blockIdx.x >> 5, kt = blockIdx.x & 31, k0 = kt * TK;
    const float* f = x + (size_t)b * CN;
    float* Fs = (float*)(sm + OFF_FS);

    // ---- load + split V (natural layout, granule ^ (chan&15))
    {
        const int l = tid & 31;
        const int mv = l * 4;
        const uint32_t vgran = (uint32_t)(l >> 1);
        const uint32_t voff8 = (uint32_t)((2 * mv) & 15);
        int c = tid >> 5;
        #pragma unroll
        for (int it = 0; it < 8; it++, c += 8) {
            const float4 v = *reinterpret_cast<const float4*>(f + (size_t)c * Nn + k0 + mv);
            *reinterpret_cast<float4*>(Fs + c * 132 + mv) = v;
            uint32_t h0, l0, h1, l1;
            split_pair(v.x, v.y, h0, l0);
            split_pair(v.z, v.w, h1, l1);
            const uint32_t go = (uint32_t)c * 256 + (((vgran ^ ((uint32_t)c & 15u)) << 4) | voff8);
            *reinterpret_cast<uint2*>(sm + OFF_VHI + go) = make_uint2(h0, h1);
            *reinterpret_cast<uint2*>(sm + OFF_VLO + go) = make_uint2(l0, l1);
        }
    }
    __syncthreads();

    // ---- transpose + split K (KT[pos][chan], granule ^ (pos&7)) + norms
    {
        const int pos = tid >> 1, c0 = (tid & 1) * 32;
        const uint32_t pg = (uint32_t)(pos & 7);
        uint32_t hi[16], lo[16];
        float ss = 0.0f;
        #pragma unroll
        for (int j = 0; j < 16; j++) {
            const float a = Fs[(c0 + 2 * j) * 132 + pos];
            const float c2 = Fs[(c0 + 2 * j + 1) * 132 + pos];
            ss += a * a + c2 * c2;
            split_pair(a, c2, hi[j], lo[j]);
        }
        const uint32_t rowb = (uint32_t)pos * 128;
        #pragma unroll
        for (int gg = 0; gg < 4; gg++) {
            const uint32_t off = rowb + ((((uint32_t)(c0 >> 3) + gg) ^ pg) << 4);
            *reinterpret_cast<uint4*>(sm + OFF_KHI + off) =
                make_uint4(hi[4 * gg], hi[4 * gg + 1], hi[4 * gg + 2], hi[4 * gg + 3]);
            *reinterpret_cast<uint4*>(sm + OFF_KLO + off) =
                make_uint4(lo[4 * gg], lo[4 * gg + 1], lo[4 * gg + 2], lo[4 * gg + 3]);
        }
        // norms: pair (tid, tid^1) share pos
        ss += __shfl_xor_sync(0xffffffffu, ss, 1);
        float nr = sqrtf(ss);
        if ((tid & 1) == 0) g_norm[b * Nn + k0 + pos] = nr;
        // warp max -> atomic
        #pragma unroll
        for (int offm = 16; offm > 0; offm >>= 1)
            nr = fmaxf(nr, __shfl_xor_sync(0xffffffffu, nr, offm));
        if ((tid & 31) == 0) atomicMax(&g_mmax[b], __float_as_uint(nr));
    }
    __syncthreads();

    // ---- bulk copy smem tiles -> global
    char* dk_hi = g_kth + (size_t)b * Nn * 128 + (size_t)k0 * 128;
    char* dk_lo = g_ktl + (size_t)b * Nn * 128 + (size_t)k0 * 128;
    char* dv_hi = g_vh + (size_t)b * 32 * 16384 + (size_t)kt * 16384;
    char* dv_lo = g_vl + (size_t)b * 32 * 16384 + (size_t)kt * 16384;
    #pragma unroll
    for (int i = 0; i < 4; i++) {
        const int o = (tid + i * 256) * 16;
        *reinterpret_cast<uint4*>(dk_hi + o) = *reinterpret_cast<const uint4*>(sm + OFF_KHI + o);
        *reinterpret_cast<uint4*>(dk_lo + o) = *reinterpret_cast<const uint4*>(sm + OFF_KLO + o);
        *reinterpret_cast<uint4*>(dv_hi + o) = *reinterpret_cast<const uint4*>(sm + OFF_VHI + o);
        *reinterpret_cast<uint4*>(dv_lo + o) = *reinterpret_cast<const uint4*>(sm + OFF_VLO + o);
    }
}

// ---------------- main kernel ----------------
__global__ void __launch_bounds__(NT, 1)
attn_hmma_kernel(const float* __restrict__ x, float* __restrict__ out) {
    extern __shared__ char sm[];
    const uint32_t smb = smem_u32(sm);
    const int tid = threadIdx.x, w = tid >> 5, lane = tid & 31;
    const int g = lane >> 2, t = lane & 3;
    const int b = blockIdx.x >> 4, q0 = (blockIdx.x & 15) * TQ;

    const char* kthb = g_kth + (size_t)b * Nn * 128;
    const char* ktlb = g_ktl + (size_t)b * Nn * 128;
    const char* vhb  = g_vh + (size_t)b * 32 * 16384;
    const char* vlb  = g_vl + (size_t)b * 32 * 16384;

    // rows this thread owns: qr, qr+8 (within q-tile)
    const int qr = 16 * w + g;
    const float mmax = __uint_as_float(g_mmax[b]);
    const float nZL0 = -(g_norm[b * Nn + q0 + qr] * mmax) * LOG2E;
    const float nZL1 = -(g_norm[b * Nn + q0 + qr + 8] * mmax) * LOG2E;

    // ---- Q A-fragments straight from converted global (one-time)
    uint32_t qh[4][4], ql[4][4];
    {
        const uint32_t pgq = (uint32_t)(qr & 7);
        const size_t r0 = (size_t)(q0 + qr) * 128 + 4 * t;
        const size_t r8 = r0 + 8 * 128;
        #pragma unroll
        for (int kc = 0; kc < 4; kc++) {
            const uint32_t g0 = (((uint32_t)(2 * kc) ^ pgq) << 4);
            const uint32_t g1 = (((uint32_t)(2 * kc + 1) ^ pgq) << 4);
            qh[kc][0] = *(const uint32_t*)(kthb + r0 + g0);
            qh[kc][1] = *(const uint32_t*)(kthb + r8 + g0);
            qh[kc][2] = *(const uint32_t*)(kthb + r0 + g1);
            qh[kc][3] = *(const uint32_t*)(kthb + r8 + g1);
            ql[kc][0] = *(const uint32_t*)(ktlb + r0 + g0);
            ql[kc][1] = *(const uint32_t*)(ktlb + r8 + g0);
            ql[kc][2] = *(const uint32_t*)(ktlb + r0 + g1);
            ql[kc][3] = *(const uint32_t*)(ktlb + r8 + g1);
        }
    }

    // ---- async tile copy: 4 chunks of 16KB per buffer
    auto issue_copy = [&](int buf, int kt) {
        const char* s[4];
        s[0] = kthb + (size_t)kt * TK * 128;
        s[1] = ktlb + (size_t)kt * TK * 128;
        s[2] = vhb + (size_t)kt * 16384;
        s[3] = vlb + (size_t)kt * 16384;
        const uint32_t base = smb + buf * BUF_BYTES;
        #pragma unroll
        for (int i = 0; i < 8; i++) {
            const int chunk = i >> 1;
            const int off = (i & 1) * 8192 + tid * 16;
            CP_ASYNC16(base + chunk * 16384 + off, s[chunk] + off);
        }
        CP_COMMIT();
    };

    issue_copy(0, 0);
    issue_copy(1, 1);

    float O[8][4];
    #pragma unroll
    for (int i = 0; i < 8; i++)
        #pragma unroll
        for (int j = 0; j < 4; j++) O[i][j] = 0.0f;
    float lac0 = 0.0f, lac1 = 0.0f;

    #pragma unroll 1
    for (int kt = 0; kt < Nn / TK; kt++) {
        if (kt == Nn / TK - 1) { CP_WAIT0(); } else { CP_WAIT1(); }
        __syncthreads();

        const char* bK_hi = sm + (kt & 1) * BUF_BYTES;
        const char* bK_lo = bK_hi + 16384;
        const char* bV_hi = bK_hi + 32768;
        const char* bV_lo = bK_hi + 49152;

        #pragma unroll 1
        for (int pc = 0; pc < 8; pc++) {
            // ---- S fragments for ntiles 2pc, 2pc+1 (3-pass bf16)
            float sa[2][4];
            #pragma unroll
            for (int u = 0; u < 2; u++) {
                const int pos = 8 * (2 * pc + u) + g;
                const uint32_t rb = (uint32_t)pos * 128 + 4 * t;
                const uint32_t pg = (uint32_t)(pos & 7);
                float* acc = sa[u];
                acc[0] = acc[1] = acc[2] = acc[3] = 0.0f;
                #pragma unroll
                for (int kc = 0; kc < 4; kc++) {
                    const uint32_t o0 = rb + (((uint32_t)(2 * kc) ^ pg) << 4);
                    const uint32_t o1 = rb + (((uint32_t)(2 * kc + 1) ^ pg) << 4);
                    uint32_t bh[2], bl[2];
                    bh[0] = *(const uint32_t*)(bK_hi + o0);
                    bh[1] = *(const uint32_t*)(bK_hi + o1);
                    bl[0] = *(const uint32_t*)(bK_lo + o0);
                    bl[1] = *(const uint32_t*)(bK_lo + o1);
                    mma16816(acc, qh[kc], bh);
                    mma16816(acc, ql[kc], bh);
                    mma16816(acc, qh[kc], bl);
                }
            }
            // ---- exp (Z-bound) + l accumulation
            float p[2][4];
            #pragma unroll
            for (int u = 0; u < 2; u++) {
                p[u][0] = ex2a(fmaf(sa[u][0], LOG2E, nZL0));
                p[u][1] = ex2a(fmaf(sa[u][1], LOG2E, nZL0));
                p[u][2] = ex2a(fmaf(sa[u][2], LOG2E, nZL1));
                p[u][3] = ex2a(fmaf(sa[u][3], LOG2E, nZL1));
                lac0 += p[u][0] + p[u][1];
                lac1 += p[u][2] + p[u][3];
            }
            // ---- pack P as PV A-fragment (register-only)
            uint32_t pah[4], pal[4];
            split_pair(p[0][0], p[0][1], pah[0], pal[0]);
            split_pair(p[0][2], p[0][3], pah[1], pal[1]);
            split_pair(p[1][0], p[1][1], pah[2], pal[2]);
            split_pair(p[1][2], p[1][3], pah[3], pal[3]);
            // ---- PV: O += Phi*Vhi + Plo*Vhi + Phi*Vlo
            #pragma unroll
            for (int ntv = 0; ntv < 8; ntv++) {
                const uint32_t chan = 8 * ntv + g;
                const uint32_t rbv = chan * 256 + 4 * t;
                const uint32_t cg = chan & 15;
                const uint32_t o0 = rbv + (((uint32_t)(2 * pc) ^ cg) << 4);
                const uint32_t o1 = rbv + (((uint32_t)(2 * pc + 1) ^ cg) << 4);
                uint32_t bh[2], bl[2];
                bh[0] = *(const uint32_t*)(bV_hi + o0);
                bh[1] = *(const uint32_t*)(bV_hi + o1);
                bl[0] = *(const uint32_t*)(bV_lo + o0);
                bl[1] = *(const uint32_t*)(bV_lo + o1);
                mma16816(O[ntv], pah, bh);
                mma16816(O[ntv], pal, bh);
                mma16816(O[ntv], pah, bl);
            }
        }
        __syncthreads();
        if (kt + 2 < Nn / TK) issue_copy(kt & 1, kt + 2);
    }

    // ---- reduce l across the 4 t-lanes sharing each row
    lac0 += __shfl_xor_sync(0xffffffffu, lac0, 1);
    lac0 += __shfl_xor_sync(0xffffffffu, lac0, 2);
    lac1 += __shfl_xor_sync(0xffffffffu, lac1, 1);
    lac1 += __shfl_xor_sync(0xffffffffu, lac1, 2);
    const float li0 = 1.0f / lac0;
    const float li1 = 1.0f / lac1;

    // ---- epilogue: out = x + O / l
    const int n0 = q0 + qr;
    const int n1 = n0 + 8;
    #pragma unroll
    for (int ntv = 0; ntv < 8; ntv++) {
        const int c = 8 * ntv + 2 * t;
        const size_t i00 = (size_t)b * CN + (size_t)c * Nn;
        out[i00 + n0]      = x[i00 + n0]      + O[ntv][0] * li0;
        out[i00 + Nn + n0] = x[i00 + Nn + n0] + O[ntv][1] * li0;
        out[i00 + n1]      = x[i00 + n1]      + O[ntv][2] * li1;
        out[i00 + Nn + n1] = x[i00 + Nn + n1] + O[ntv][3] * li1;
    }
}

extern "C" void kernel_launch(void* const* d_in, const int* in_sizes, int n_in,
                              void* d_out, int out_size) {
    const float* x = (const float*)d_in[0];
    float* out = (float*)d_out;
    (void)in_sizes; (void)n_in; (void)out_size;

    cudaFuncSetAttribute(convert_kernel,
                         cudaFuncAttributeMaxDynamicSharedMemorySize, CONV_SMEM);
    cudaFuncSetAttribute(attn_hmma_kernel,
                         cudaFuncAttributeMaxDynamicSharedMemorySize, MAIN_SMEM);

    init_mmax_kernel<<<1, 32>>>();
    convert_kernel<<<Bq * 32, 256, CONV_SMEM>>>(x);
    attn_hmma_kernel<<<Bq * 16, NT, MAIN_SMEM>>>(x, out);
}

// round 9
// speedup vs baseline: 5.9273x; 1.2026x over previous
#include <cuda_runtime.h>
#include <cuda_bf16.h>
#include <math.h>
#include <stdint.h>

static constexpr int Bq = 8, Cc = 64, Nn = 4096, TQ = 256, TK = 128, NT = 512;
static constexpr long CN = (long)Cc * Nn;
static constexpr float LOG2E = 1.4426950408889634f;

// ---- persistent converted operands (swizzle baked in)
__device__ char g_kth[(size_t)Bq * Nn * 128];      // KT[b][pos][chan] bf16-hi, 128B rows
__device__ char g_ktl[(size_t)Bq * Nn * 128];      // bf16-lo
__device__ char g_v32[(size_t)Bq * 32 * 32768];    // V[b][kt][chan][pos] tf32, 512B rows
__device__ float g_norm[Bq * Nn];
__device__ float g_tilemax[Bq * 32];

// ---- convert-kernel smem layout (bytes)
static constexpr int OFF_FS  = 0;                  // fp32 staging [64][132]
static constexpr int OFF_KHI = 33792;
static constexpr int OFF_KLO = OFF_KHI + 16384;
static constexpr int OFF_V32 = OFF_KLO + 16384;
static constexpr int CONV_SMEM = OFF_V32 + 32768;  // 99328 B

// ---- main-kernel smem: 2 x 64KB buffers {KHI 16K, KLO 16K, V32 32K}
static constexpr int BUF_BYTES = 65536;
static constexpr int MAIN_SMEM = 2 * BUF_BYTES;    // 131072 B

// ---------------- helpers ----------------
__device__ __forceinline__ float ex2a(float x) {
    float y;
    asm("ex2.approx.f32 %0, %1;" : "=f"(y) : "f"(x));
    return y;
}
__device__ __forceinline__ uint32_t cvt2(float e1_hi, float e0_lo) {
    uint32_t r;
    asm("cvt.rn.bf16x2.f32 %0, %1, %2;" : "=r"(r) : "f"(e1_hi), "f"(e0_lo));
    return r;
}
__device__ __forceinline__ void split_pair(float e0, float e1, uint32_t& h, uint32_t& l) {
    h = cvt2(e1, e0);
    const float h0 = __uint_as_float(h << 16);
    const float h1 = __uint_as_float(h & 0xFFFF0000u);
    l = cvt2(e1 - h1, e0 - h0);
}
__device__ __forceinline__ uint32_t tf32r(float x) {
    uint32_t r;
    asm("cvt.rna.tf32.f32 %0, %1;" : "=r"(r) : "f"(x));
    return r;
}
__device__ __forceinline__ void mma16816(float* d, const uint32_t* a, const uint32_t* b) {
    asm volatile(
        "mma.sync.aligned.m16n8k16.row.col.f32.bf16.bf16.f32 "
        "{%0,%1,%2,%3}, {%4,%5,%6,%7}, {%8,%9}, {%0,%1,%2,%3};"
        : "+f"(d[0]), "+f"(d[1]), "+f"(d[2]), "+f"(d[3])
        : "r"(a[0]), "r"(a[1]), "r"(a[2]), "r"(a[3]), "r"(b[0]), "r"(b[1]));
}
__device__ __forceinline__ void mma_tf32(float* d, const uint32_t* a, uint32_t b0, uint32_t b1) {
    asm volatile(
        "mma.sync.aligned.m16n8k8.row.col.f32.tf32.tf32.f32 "
        "{%0,%1,%2,%3}, {%4,%5,%6,%7}, {%8,%9}, {%0,%1,%2,%3};"
        : "+f"(d[0]), "+f"(d[1]), "+f"(d[2]), "+f"(d[3])
        : "r"(a[0]), "r"(a[1]), "r"(a[2]), "r"(a[3]), "r"(b0), "r"(b1));
}
__device__ __forceinline__ uint32_t smem_u32(const void* p) {
    uint32_t a;
    asm("{ .reg .u64 t; cvta.to.shared.u64 t, %1; cvt.u32.u64 %0, t; }" : "=r"(a) : "l"(p));
    return a;
}
#define CP_ASYNC16(dst, src) \
    asm volatile("cp.async.cg.shared.global [%0], [%1], 16;" :: "r"(dst), "l"(src) : "memory")
#define CP_COMMIT() asm volatile("cp.async.commit_group;" ::: "memory")
#define CP_WAIT1()  asm volatile("cp.async.wait_group 1;" ::: "memory")
#define CP_WAIT0()  asm volatile("cp.async.wait_group 0;" ::: "memory")

// ---------------- pre-pass: convert (b, kt) tile ----------------
__global__ void __launch_bounds__(256)
convert_kernel(const float* __restrict__ x) {
    extern __shared__ char sm[];
    __shared__ float wmax[8];
    const int tid = threadIdx.x;
    const int b = blockIdx.x >> 5, kt = blockIdx.x & 31, k0 = kt * TK;
    const float* f = x + (size_t)b * CN;
    float* Fs = (float*)(sm + OFF_FS);

    // ---- load fp32 tile + V as tf32 fp32 (natural [chan][pos], 8B-granule swizzle)
    {
        const int l = tid & 31;
        const int mv = l * 4;
        int c = tid >> 5;
        #pragma unroll
        for (int it = 0; it < 8; it++, c += 8) {
            const float4 v = *reinterpret_cast<const float4*>(f + (size_t)c * Nn + k0 + mv);
            *reinterpret_cast<float4*>(Fs + c * 132 + mv) = v;
            const uint32_t swz = ((uint32_t)c & 7u) << 1;
            const uint32_t g80 = (uint32_t)(mv >> 1);
            char* vb = sm + OFF_V32 + c * 512;
            *reinterpret_cast<uint2*>(vb + ((g80 ^ swz) << 3)) = make_uint2(tf32r(v.x), tf32r(v.y));
            *reinterpret_cast<uint2*>(vb + (((g80 + 1) ^ swz) << 3)) = make_uint2(tf32r(v.z), tf32r(v.w));
        }
    }
    __syncthreads();

    // ---- transpose + split K (KT[pos][chan] bf16 hi/lo, granule ^ (pos&7)) + norms
    {
        const int pos = tid >> 1, c0 = (tid & 1) * 32;
        const uint32_t pg = (uint32_t)(pos & 7);
        uint32_t hi[16], lo[16];
        float ss = 0.0f;
        #pragma unroll
        for (int j = 0; j < 16; j++) {
            const float a = Fs[(c0 + 2 * j) * 132 + pos];
            const float c2 = Fs[(c0 + 2 * j + 1) * 132 + pos];
            ss += a * a + c2 * c2;
            split_pair(a, c2, hi[j], lo[j]);
        }
        const uint32_t rowb = (uint32_t)pos * 128;
        #pragma unroll
        for (int gg = 0; gg < 4; gg++) {
            const uint32_t off = rowb + ((((uint32_t)(c0 >> 3) + gg) ^ pg) << 4);
            *reinterpret_cast<uint4*>(sm + OFF_KHI + off) =
                make_uint4(hi[4 * gg], hi[4 * gg + 1], hi[4 * gg + 2], hi[4 * gg + 3]);
            *reinterpret_cast<uint4*>(sm + OFF_KLO + off) =
                make_uint4(lo[4 * gg], lo[4 * gg + 1], lo[4 * gg + 2], lo[4 * gg + 3]);
        }
        // norms: pair (tid, tid^1) share pos
        ss += __shfl_xor_sync(0xffffffffu, ss, 1);
        float nr = sqrtf(ss);
        if ((tid & 1) == 0) g_norm[b * Nn + k0 + pos] = nr;
        #pragma unroll
        for (int offm = 16; offm > 0; offm >>= 1)
            nr = fmaxf(nr, __shfl_xor_sync(0xffffffffu, nr, offm));
        if ((tid & 31) == 0) wmax[tid >> 5] = nr;
    }
    __syncthreads();

    if (tid == 0) {
        float m = wmax[0];
        #pragma unroll
        for (int i = 1; i < 8; i++) m = fmaxf(m, wmax[i]);
        g_tilemax[b * 32 + kt] = m;
    }

    // ---- bulk copy smem tiles -> global
    char* dk_hi = g_kth + (size_t)b * Nn * 128 + (size_t)k0 * 128;
    char* dk_lo = g_ktl + (size_t)b * Nn * 128 + (size_t)k0 * 128;
    char* dv    = g_v32 + (size_t)b * 32 * 32768 + (size_t)kt * 32768;
    #pragma unroll
    for (int i = 0; i < 4; i++) {
        const int o = (tid + i * 256) * 16;
        *reinterpret_cast<uint4*>(dk_hi + o) = *reinterpret_cast<const uint4*>(sm + OFF_KHI + o);
        *reinterpret_cast<uint4*>(dk_lo + o) = *reinterpret_cast<const uint4*>(sm + OFF_KLO + o);
    }
    #pragma unroll
    for (int i = 0; i < 8; i++) {
        const int o = (tid + i * 256) * 16;
        *reinterpret_cast<uint4*>(dv + o) = *reinterpret_cast<const uint4*>(sm + OFF_V32 + o);
    }
}

// ---------------- main kernel ----------------
__global__ void __launch_bounds__(NT, 1)
attn_hmma_kernel(const float* __restrict__ x, float* __restrict__ out) {
    extern __shared__ char sm[];
    const uint32_t smb = smem_u32(sm);
    const int tid = threadIdx.x, w = tid >> 5, lane = tid & 31;
    const int g = lane >> 2, t = lane & 3;
    const int b = blockIdx.x >> 4, q0 = (blockIdx.x & 15) * TQ;

    const char* kthb = g_kth + (size_t)b * Nn * 128;
    const char* ktlb = g_ktl + (size_t)b * Nn * 128;
    const char* v32b = g_v32 + (size_t)b * 32 * 32768;

    // per-batch max norm from per-tile maxes
    const float* tmx = g_tilemax + b * 32;
    float mmax = tmx[0];
    #pragma unroll
    for (int i = 1; i < 32; i++) mmax = fmaxf(mmax, tmx[i]);

    // rows this thread owns: qr, qr+8 (within q-tile)
    const int qr = 16 * w + g;
    const float nZL0 = -(g_norm[b * Nn + q0 + qr] * mmax) * LOG2E;
    const float nZL1 = -(g_norm[b * Nn + q0 + qr + 8] * mmax) * LOG2E;

    // ---- Q A-fragments straight from converted global (one-time)
    uint32_t qh[4][4], ql[4][4];
    {
        const uint32_t pgq = (uint32_t)(qr & 7);
        const size_t r0 = (size_t)(q0 + qr) * 128 + 4 * t;
        const size_t r8 = r0 + 8 * 128;
        #pragma unroll
        for (int kc = 0; kc < 4; kc++) {
            const uint32_t g0 = (((uint32_t)(2 * kc) ^ pgq) << 4);
            const uint32_t g1 = (((uint32_t)(2 * kc + 1) ^ pgq) << 4);
            qh[kc][0] = *(const uint32_t*)(kthb + r0 + g0);
            qh[kc][1] = *(const uint32_t*)(kthb + r8 + g0);
            qh[kc][2] = *(const uint32_t*)(kthb + r0 + g1);
            qh[kc][3] = *(const uint32_t*)(kthb + r8 + g1);
            ql[kc][0] = *(const uint32_t*)(ktlb + r0 + g0);
            ql[kc][1] = *(const uint32_t*)(ktlb + r8 + g0);
            ql[kc][2] = *(const uint32_t*)(ktlb + r0 + g1);
            ql[kc][3] = *(const uint32_t*)(ktlb + r8 + g1);
        }
    }

    // ---- async tile copy: {KHI 16K, KLO 16K, V32 32K} in 8KB slabs
    auto issue_copy = [&](int buf, int kt) {
        const char* s0 = kthb + (size_t)kt * TK * 128;
        const char* s1 = ktlb + (size_t)kt * TK * 128;
        const char* s2 = v32b + (size_t)kt * 32768;
        const uint32_t base = smb + buf * BUF_BYTES;
        const int off = tid * 16;
        #pragma unroll
        for (int i = 0; i < 2; i++)
            CP_ASYNC16(base + i * 8192 + off, s0 + i * 8192 + off);
        #pragma unroll
        for (int i = 0; i < 2; i++)
            CP_ASYNC16(base + 16384 + i * 8192 + off, s1 + i * 8192 + off);
        #pragma unroll
        for (int i = 0; i < 4; i++)
            CP_ASYNC16(base + 32768 + i * 8192 + off, s2 + i * 8192 + off);
        CP_COMMIT();
    };

    issue_copy(0, 0);
    issue_copy(1, 1);

    float O[8][4];
    #pragma unroll
    for (int i = 0; i < 8; i++)
        #pragma unroll
        for (int j = 0; j < 4; j++) O[i][j] = 0.0f;
    float lac0 = 0.0f, lac1 = 0.0f;

    #pragma unroll 1
    for (int kt = 0; kt < Nn / TK; kt++) {
        if (kt == Nn / TK - 1) { CP_WAIT0(); } else { CP_WAIT1(); }
        __syncthreads();

        const char* bK_hi = sm + (kt & 1) * BUF_BYTES;
        const char* bK_lo = bK_hi + 16384;
        const char* bV    = bK_hi + 32768;

        #pragma unroll 1
        for (int pc = 0; pc < 8; pc++) {
            // ---- S fragments for ntiles 2pc, 2pc+1 (3-pass bf16)
            float sa[2][4];
            #pragma unroll
            for (int u = 0; u < 2; u++) {
                const int pos = 8 * (2 * pc + u) + g;
                const uint32_t rb = (uint32_t)pos * 128 + 4 * t;
                const uint32_t pg = (uint32_t)(pos & 7);
                float* acc = sa[u];
                acc[0] = acc[1] = acc[2] = acc[3] = 0.0f;
                #pragma unroll
                for (int kc = 0; kc < 4; kc++) {
                    const uint32_t o0 = rb + (((uint32_t)(2 * kc) ^ pg) << 4);
                    const uint32_t o1 = rb + (((uint32_t)(2 * kc + 1) ^ pg) << 4);
                    uint32_t bh[2], bl[2];
                    bh[0] = *(const uint32_t*)(bK_hi + o0);
                    bh[1] = *(const uint32_t*)(bK_hi + o1);
                    bl[0] = *(const uint32_t*)(bK_lo + o0);
                    bl[1] = *(const uint32_t*)(bK_lo + o1);
                    mma16816(acc, qh[kc], bh);
                    mma16816(acc, ql[kc], bh);
                    mma16816(acc, qh[kc], bl);
                }
            }
            // ---- exp (Z-bound, no rescale) + l accumulation
            float p[2][4];
            #pragma unroll
            for (int u = 0; u < 2; u++) {
                p[u][0] = ex2a(fmaf(sa[u][0], LOG2E, nZL0));
                p[u][1] = ex2a(fmaf(sa[u][1], LOG2E, nZL0));
                p[u][2] = ex2a(fmaf(sa[u][2], LOG2E, nZL1));
                p[u][3] = ex2a(fmaf(sa[u][3], LOG2E, nZL1));
                lac0 += p[u][0] + p[u][1];
                lac1 += p[u][2] + p[u][3];
            }
            // ---- P as tf32 A-fragments (direct register mapping, no shuffles)
            uint32_t at0[4], at1[4];
            at0[0] = tf32r(p[0][0]); at0[1] = tf32r(p[0][2]);
            at0[2] = tf32r(p[0][1]); at0[3] = tf32r(p[0][3]);
            at1[0] = tf32r(p[1][0]); at1[1] = tf32r(p[1][2]);
            at1[2] = tf32r(p[1][1]); at1[3] = tf32r(p[1][3]);
            // ---- PV: single-pass tf32, V natural layout, LDS.64 per mma
            const uint32_t g80 = (uint32_t)(8 * pc + t);
            #pragma unroll
            for (int ntv = 0; ntv < 8; ntv++) {
                const uint32_t rb = (uint32_t)(8 * ntv + g) * 512;
                const uint32_t swz = (uint32_t)g << 1;
                const uint2 b0 = *(const uint2*)(bV + rb + ((g80 ^ swz) << 3));
                const uint2 b1 = *(const uint2*)(bV + rb + (((g80 + 4) ^ swz) << 3));
                mma_tf32(O[ntv], at0, b0.x, b0.y);
                mma_tf32(O[ntv], at1, b1.x, b1.y);
            }
        }
        __syncthreads();
        if (kt + 2 < Nn / TK) issue_copy(kt & 1, kt + 2);
    }

    // ---- reduce l across the 4 t-lanes sharing each row
    lac0 += __shfl_xor_sync(0xffffffffu, lac0, 1);
    lac0 += __shfl_xor_sync(0xffffffffu, lac0, 2);
    lac1 += __shfl_xor_sync(0xffffffffu, lac1, 1);
    lac1 += __shfl_xor_sync(0xffffffffu, lac1, 2);
    const float li0 = 1.0f / lac0;
    const float li1 = 1.0f / lac1;

    // ---- epilogue: out = x + O / l
    const int n0 = q0 + qr;
    const int n1 = n0 + 8;
    #pragma unroll
    for (int ntv = 0; ntv < 8; ntv++) {
        const int c = 8 * ntv + 2 * t;
        const size_t i00 = (size_t)b * CN + (size_t)c * Nn;
        out[i00 + n0]      = x[i00 + n0]      + O[ntv][0] * li0;
        out[i00 + Nn + n0] = x[i00 + Nn + n0] + O[ntv][1] * li0;
        out[i00 + n1]      = x[i00 + n1]      + O[ntv][2] * li1;
        out[i00 + Nn + n1] = x[i00 + Nn + n1] + O[ntv][3] * li1;
    }
}

extern "C" void kernel_launch(void* const* d_in, const int* in_sizes, int n_in,
                              void* d_out, int out_size) {
    const float* x = (const float*)d_in[0];
    float* out = (float*)d_out;
    (void)in_sizes; (void)n_in; (void)out_size;

    cudaFuncSetAttribute(convert_kernel,
                         cudaFuncAttributeMaxDynamicSharedMemorySize, CONV_SMEM);
    cudaFuncSetAttribute(attn_hmma_kernel,
                         cudaFuncAttributeMaxDynamicSharedMemorySize, MAIN_SMEM);

    convert_kernel<<<Bq * 32, 256, CONV_SMEM>>>(x);
    attn_hmma_kernel<<<Bq * 16, NT, MAIN_SMEM>>>(x, out);
}

// round 10
// speedup vs baseline: 6.1573x; 1.0388x over previous
#include <cuda_runtime.h>
#include <cuda_bf16.h>
#include <math.h>
#include <stdint.h>

static constexpr int Bq = 8, Cc = 64, Nn = 4096, TQ = 256, TK = 128, NT = 256;
static constexpr long CN = (long)Cc * Nn;
static constexpr float LOG2E = 1.4426950408889634f;

// ---- persistent converted operands (swizzle baked in)
__device__ char g_kth[(size_t)Bq * Nn * 128];      // KT[b][pos][chan] bf16-hi, 128B rows
__device__ char g_ktl[(size_t)Bq * Nn * 128];      // bf16-lo
__device__ char g_v32[(size_t)Bq * 32 * 32768];    // V[b][kt][chan][pos] tf32, 512B rows
__device__ float g_norm[Bq * Nn];
__device__ float g_tilemax[Bq * 32];

// ---- convert-kernel smem layout (bytes)
static constexpr int OFF_FS  = 0;                  // fp32 staging [64][132]
static constexpr int OFF_KHI = 33792;
static constexpr int OFF_KLO = OFF_KHI + 16384;
static constexpr int OFF_V32 = OFF_KLO + 16384;
static constexpr int CONV_SMEM = OFF_V32 + 32768;  // 99328 B

// ---- main-kernel smem: 2 x 64KB buffers {KHI 16K, KLO 16K, V32 32K}
static constexpr int BUF_BYTES = 65536;
static constexpr int MAIN_SMEM = 2 * BUF_BYTES;    // 131072 B

// ---------------- helpers ----------------
__device__ __forceinline__ float ex2a(float x) {
    float y;
    asm("ex2.approx.f32 %0, %1;" : "=f"(y) : "f"(x));
    return y;
}
__device__ __forceinline__ uint32_t cvt2(float e1_hi, float e0_lo) {
    uint32_t r;
    asm("cvt.rn.bf16x2.f32 %0, %1, %2;" : "=r"(r) : "f"(e1_hi), "f"(e0_lo));
    return r;
}
__device__ __forceinline__ void split_pair(float e0, float e1, uint32_t& h, uint32_t& l) {
    h = cvt2(e1, e0);
    const float h0 = __uint_as_float(h << 16);
    const float h1 = __uint_as_float(h & 0xFFFF0000u);
    l = cvt2(e1 - h1, e0 - h0);
}
__device__ __forceinline__ uint32_t tf32r(float x) {
    uint32_t r;
    asm("cvt.rna.tf32.f32 %0, %1;" : "=r"(r) : "f"(x));
    return r;
}
__device__ __forceinline__ void mma16816(float* d, const uint32_t* a, const uint32_t* b) {
    asm volatile(
        "mma.sync.aligned.m16n8k16.row.col.f32.bf16.bf16.f32 "
        "{%0,%1,%2,%3}, {%4,%5,%6,%7}, {%8,%9}, {%0,%1,%2,%3};"
        : "+f"(d[0]), "+f"(d[1]), "+f"(d[2]), "+f"(d[3])
        : "r"(a[0]), "r"(a[1]), "r"(a[2]), "r"(a[3]), "r"(b[0]), "r"(b[1]));
}
__device__ __forceinline__ void mma_tf32(float* d, const uint32_t* a, uint32_t b0, uint32_t b1) {
    asm volatile(
        "mma.sync.aligned.m16n8k8.row.col.f32.tf32.tf32.f32 "
        "{%0,%1,%2,%3}, {%4,%5,%6,%7}, {%8,%9}, {%0,%1,%2,%3};"
        : "+f"(d[0]), "+f"(d[1]), "+f"(d[2]), "+f"(d[3])
        : "r"(a[0]), "r"(a[1]), "r"(a[2]), "r"(a[3]), "r"(b0), "r"(b1));
}
__device__ __forceinline__ uint32_t smem_u32(const void* p) {
    uint32_t a;
    asm("{ .reg .u64 t; cvta.to.shared.u64 t, %1; cvt.u32.u64 %0, t; }" : "=r"(a) : "l"(p));
    return a;
}
#define CP_ASYNC16(dst, src) \
    asm volatile("cp.async.cg.shared.global [%0], [%1], 16;" :: "r"(dst), "l"(src) : "memory")
#define CP_COMMIT() asm volatile("cp.async.commit_group;" ::: "memory")
#define CP_WAIT1()  asm volatile("cp.async.wait_group 1;" ::: "memory")
#define CP_WAIT0()  asm volatile("cp.async.wait_group 0;" ::: "memory")

// ---------------- pre-pass: convert (b, kt) tile ----------------
__global__ void __launch_bounds__(256)
convert_kernel(const float* __restrict__ x) {
    extern __shared__ char sm[];
    __shared__ float wmax[8];
    const int tid = threadIdx.x;
    const int b = blockIdx.x >> 5, kt = blockIdx.x & 31, k0 = kt * TK;
    const float* f = x + (size_t)b * CN;
    float* Fs = (float*)(sm + OFF_FS);

    // ---- load fp32 tile + V as tf32 (natural [chan][pos], 8B-granule swizzle)
    {
        const int l = tid & 31;
        const int mv = l * 4;
        int c = tid >> 5;
        #pragma unroll
        for (int it = 0; it < 8; it++, c += 8) {
            const float4 v = *reinterpret_cast<const float4*>(f + (size_t)c * Nn + k0 + mv);
            *reinterpret_cast<float4*>(Fs + c * 132 + mv) = v;
            const uint32_t swz = ((uint32_t)c & 7u) << 1;
            const uint32_t g80 = (uint32_t)(mv >> 1);
            char* vb = sm + OFF_V32 + c * 512;
            *reinterpret_cast<uint2*>(vb + ((g80 ^ swz) << 3)) = make_uint2(tf32r(v.x), tf32r(v.y));
            *reinterpret_cast<uint2*>(vb + (((g80 + 1) ^ swz) << 3)) = make_uint2(tf32r(v.z), tf32r(v.w));
        }
    }
    __syncthreads();

    // ---- transpose + split K (KT[pos][chan] bf16 hi/lo, granule ^ (pos&7)) + norms
    {
        const int pos = tid >> 1, c0 = (tid & 1) * 32;
        const uint32_t pg = (uint32_t)(pos & 7);
        uint32_t hi[16], lo[16];
        float ss = 0.0f;
        #pragma unroll
        for (int j = 0; j < 16; j++) {
            const float a = Fs[(c0 + 2 * j) * 132 + pos];
            const float c2 = Fs[(c0 + 2 * j + 1) * 132 + pos];
            ss += a * a + c2 * c2;
            split_pair(a, c2, hi[j], lo[j]);
        }
        const uint32_t rowb = (uint32_t)pos * 128;
        #pragma unroll
        for (int gg = 0; gg < 4; gg++) {
            const uint32_t off = rowb + ((((uint32_t)(c0 >> 3) + gg) ^ pg) << 4);
            *reinterpret_cast<uint4*>(sm + OFF_KHI + off) =
                make_uint4(hi[4 * gg], hi[4 * gg + 1], hi[4 * gg + 2], hi[4 * gg + 3]);
            *reinterpret_cast<uint4*>(sm + OFF_KLO + off) =
                make_uint4(lo[4 * gg], lo[4 * gg + 1], lo[4 * gg + 2], lo[4 * gg + 3]);
        }
        // norms: pair (tid, tid^1) share pos
        ss += __shfl_xor_sync(0xffffffffu, ss, 1);
        float nr = sqrtf(ss);
        if ((tid & 1) == 0) g_norm[b * Nn + k0 + pos] = nr;
        #pragma unroll
        for (int offm = 16; offm > 0; offm >>= 1)
            nr = fmaxf(nr, __shfl_xor_sync(0xffffffffu, nr, offm));
        if ((tid & 31) == 0) wmax[tid >> 5] = nr;
    }
    __syncthreads();

    if (tid == 0) {
        float m = wmax[0];
        #pragma unroll
        for (int i = 1; i < 8; i++) m = fmaxf(m, wmax[i]);
        g_tilemax[b * 32 + kt] = m;
    }

    // ---- bulk copy smem tiles -> global
    char* dk_hi = g_kth + (size_t)b * Nn * 128 + (size_t)k0 * 128;
    char* dk_lo = g_ktl + (size_t)b * Nn * 128 + (size_t)k0 * 128;
    char* dv    = g_v32 + (size_t)b * 32 * 32768 + (size_t)kt * 32768;
    #pragma unroll
    for (int i = 0; i < 4; i++) {
        const int o = (tid + i * 256) * 16;
        *reinterpret_cast<uint4*>(dk_hi + o) = *reinterpret_cast<const uint4*>(sm + OFF_KHI + o);
        *reinterpret_cast<uint4*>(dk_lo + o) = *reinterpret_cast<const uint4*>(sm + OFF_KLO + o);
    }
    #pragma unroll
    for (int i = 0; i < 8; i++) {
        const int o = (tid + i * 256) * 16;
        *reinterpret_cast<uint4*>(dv + o) = *reinterpret_cast<const uint4*>(sm + OFF_V32 + o);
    }
}

// ---------------- main kernel: 8 warps, 32 q-rows per warp (2 m-tiles) ----------------
__global__ void __launch_bounds__(NT, 1)
attn_hmma_kernel(const float* __restrict__ x, float* __restrict__ out) {
    extern __shared__ char sm[];
    const uint32_t smb = smem_u32(sm);
    const int tid = threadIdx.x, w = tid >> 5, lane = tid & 31;
    const int g = lane >> 2, t = lane & 3;
    const int b = blockIdx.x >> 4, q0 = (blockIdx.x & 15) * TQ;

    const char* kthb = g_kth + (size_t)b * Nn * 128;
    const char* ktlb = g_ktl + (size_t)b * Nn * 128;
    const char* v32b = g_v32 + (size_t)b * 32 * 32768;

    // per-batch max norm from per-tile maxes
    const float* tmx = g_tilemax + b * 32;
    float mmax = tmx[0];
    #pragma unroll
    for (int i = 1; i < 32; i++) mmax = fmaxf(mmax, tmx[i]);

    // rows this thread owns: (32w + 16mt + g) and +8, mt = 0,1
    float nZ[2][2];
    #pragma unroll
    for (int mt = 0; mt < 2; mt++) {
        const int qr = 32 * w + 16 * mt + g;
        nZ[mt][0] = -(g_norm[b * Nn + q0 + qr] * mmax) * LOG2E;
        nZ[mt][1] = -(g_norm[b * Nn + q0 + qr + 8] * mmax) * LOG2E;
    }

    // ---- Q A-fragments straight from converted global (one-time)
    uint32_t qh[2][4][4], ql[2][4][4];
    #pragma unroll
    for (int mt = 0; mt < 2; mt++) {
        const int qr = 32 * w + 16 * mt + g;
        const uint32_t pgq = (uint32_t)(qr & 7);
        const size_t r0 = (size_t)(q0 + qr) * 128 + 4 * t;
        const size_t r8 = r0 + 8 * 128;
        #pragma unroll
        for (int kc = 0; kc < 4; kc++) {
            const uint32_t g0 = (((uint32_t)(2 * kc) ^ pgq) << 4);
            const uint32_t g1 = (((uint32_t)(2 * kc + 1) ^ pgq) << 4);
            qh[mt][kc][0] = *(const uint32_t*)(kthb + r0 + g0);
            qh[mt][kc][1] = *(const uint32_t*)(kthb + r8 + g0);
            qh[mt][kc][2] = *(const uint32_t*)(kthb + r0 + g1);
            qh[mt][kc][3] = *(const uint32_t*)(kthb + r8 + g1);
            ql[mt][kc][0] = *(const uint32_t*)(ktlb + r0 + g0);
            ql[mt][kc][1] = *(const uint32_t*)(ktlb + r8 + g0);
            ql[mt][kc][2] = *(const uint32_t*)(ktlb + r0 + g1);
            ql[mt][kc][3] = *(const uint32_t*)(ktlb + r8 + g1);
        }
    }

    // ---- async tile copy: {KHI 16K, KLO 16K, V32 32K}, 256 threads
    auto issue_copy = [&](int buf, int kt) {
        const char* s0 = kthb + (size_t)kt * TK * 128;
        const char* s1 = ktlb + (size_t)kt * TK * 128;
        const char* s2 = v32b + (size_t)kt * 32768;
        const uint32_t base = smb + buf * BUF_BYTES;
        const int off = tid * 16;
        #pragma unroll
        for (int i = 0; i < 4; i++)
            CP_ASYNC16(base + i * 4096 + off, s0 + i * 4096 + off);
        #pragma unroll
        for (int i = 0; i < 4; i++)
            CP_ASYNC16(base + 16384 + i * 4096 + off, s1 + i * 4096 + off);
        #pragma unroll
        for (int i = 0; i < 8; i++)
            CP_ASYNC16(base + 32768 + i * 4096 + off, s2 + i * 4096 + off);
        CP_COMMIT();
    };

    issue_copy(0, 0);
    issue_copy(1, 1);

    float O[2][8][4];
    #pragma unroll
    for (int mt = 0; mt < 2; mt++)
        #pragma unroll
        for (int i = 0; i < 8; i++)
            #pragma unroll
            for (int j = 0; j < 4; j++) O[mt][i][j] = 0.0f;
    float lac[2][2] = {{0.0f, 0.0f}, {0.0f, 0.0f}};

    #pragma unroll 1
    for (int kt = 0; kt < Nn / TK; kt++) {
        if (kt == Nn / TK - 1) { CP_WAIT0(); } else { CP_WAIT1(); }
        __syncthreads();

        const char* bK_hi = sm + (kt & 1) * BUF_BYTES;
        const char* bK_lo = bK_hi + 16384;
        const char* bV    = bK_hi + 32768;

        #pragma unroll 1
        for (int pc = 0; pc < 8; pc++) {
            // ---- S fragments: independent HH / MIX accumulator chains for ILP
            float sHH[2][2][4], sMX[2][2][4];
            #pragma unroll
            for (int mt = 0; mt < 2; mt++)
                #pragma unroll
                for (int u = 0; u < 2; u++)
                    #pragma unroll
                    for (int j = 0; j < 4; j++) { sHH[mt][u][j] = 0.0f; sMX[mt][u][j] = 0.0f; }

            #pragma unroll
            for (int u = 0; u < 2; u++) {
                const int pos = 8 * (2 * pc + u) + g;
                const uint32_t rb = (uint32_t)pos * 128 + 4 * t;
                const uint32_t pg = (uint32_t)(pos & 7);
                #pragma unroll
                for (int kc = 0; kc < 4; kc++) {
                    const uint32_t o0 = rb + (((uint32_t)(2 * kc) ^ pg) << 4);
                    const uint32_t o1 = rb + (((uint32_t)(2 * kc + 1) ^ pg) << 4);
                    uint32_t bh[2], bl[2];
                    bh[0] = *(const uint32_t*)(bK_hi + o0);
                    bh[1] = *(const uint32_t*)(bK_hi + o1);
                    bl[0] = *(const uint32_t*)(bK_lo + o0);
                    bl[1] = *(const uint32_t*)(bK_lo + o1);
                    mma16816(sHH[0][u], qh[0][kc], bh);
                    mma16816(sHH[1][u], qh[1][kc], bh);
                    mma16816(sMX[0][u], ql[0][kc], bh);
                    mma16816(sMX[1][u], ql[1][kc], bh);
                    mma16816(sMX[0][u], qh[0][kc], bl);
                    mma16816(sMX[1][u], qh[1][kc], bl);
                }
            }
            // ---- exp (Z-bound) + l accumulation + tf32 A-fragments
            uint32_t at[2][2][4];
            #pragma unroll
            for (int mt = 0; mt < 2; mt++) {
                #pragma unroll
                for (int u = 0; u < 2; u++) {
                    const float p0 = ex2a(fmaf(sHH[mt][u][0] + sMX[mt][u][0], LOG2E, nZ[mt][0]));
                    const float p1 = ex2a(fmaf(sHH[mt][u][1] + sMX[mt][u][1], LOG2E, nZ[mt][0]));
                    const float p2 = ex2a(fmaf(sHH[mt][u][2] + sMX[mt][u][2], LOG2E, nZ[mt][1]));
                    const float p3 = ex2a(fmaf(sHH[mt][u][3] + sMX[mt][u][3], LOG2E, nZ[mt][1]));
                    lac[mt][0] += p0 + p1;
                    lac[mt][1] += p2 + p3;
                    at[mt][u][0] = tf32r(p0);
                    at[mt][u][1] = tf32r(p2);
                    at[mt][u][2] = tf32r(p1);
                    at[mt][u][3] = tf32r(p3);
                }
            }
            // ---- PV: single-pass tf32, V fragments shared across both m-tiles
            const uint32_t g80 = (uint32_t)(8 * pc + t);
            const uint32_t swz = (uint32_t)g << 1;
            #pragma unroll
            for (int ntv = 0; ntv < 8; ntv++) {
                const uint32_t rb = (uint32_t)(8 * ntv + g) * 512;
                const uint2 b0 = *(const uint2*)(bV + rb + ((g80 ^ swz) << 3));
                const uint2 b1 = *(const uint2*)(bV + rb + (((g80 + 4) ^ swz) << 3));
                mma_tf32(O[0][ntv], at[0][0], b0.x, b0.y);
                mma_tf32(O[1][ntv], at[1][0], b0.x, b0.y);
                mma_tf32(O[0][ntv], at[0][1], b1.x, b1.y);
                mma_tf32(O[1][ntv], at[1][1], b1.x, b1.y);
            }
        }
        __syncthreads();
        if (kt + 2 < Nn / TK) issue_copy(kt & 1, kt + 2);
    }

    // ---- reduce l across the 4 t-lanes sharing each row
    #pragma unroll
    for (int mt = 0; mt < 2; mt++) {
        lac[mt][0] += __shfl_xor_sync(0xffffffffu, lac[mt][0], 1);
        lac[mt][0] += __shfl_xor_sync(0xffffffffu, lac[mt][0], 2);
        lac[mt][1] += __shfl_xor_sync(0xffffffffu, lac[mt][1], 1);
        lac[mt][1] += __shfl_xor_sync(0xffffffffu, lac[mt][1], 2);
    }

    // ---- epilogue: out = x + O / l
    #pragma unroll
    for (int mt = 0; mt < 2; mt++) {
        const float li0 = 1.0f / lac[mt][0];
        const float li1 = 1.0f / lac[mt][1];
        const int n0 = q0 + 32 * w + 16 * mt + g;
        const int n1 = n0 + 8;
        #pragma unroll
        for (int ntv = 0; ntv < 8; ntv++) {
            const int c = 8 * ntv + 2 * t;
            const size_t i00 = (size_t)b * CN + (size_t)c * Nn;
            out[i00 + n0]      = x[i00 + n0]      + O[mt][ntv][0] * li0;
            out[i00 + Nn + n0] = x[i00 + Nn + n0] + O[mt][ntv][1] * li0;
            out[i00 + n1]      = x[i00 + n1]      + O[mt][ntv][2] * li1;
            out[i00 + Nn + n1] = x[i00 + Nn + n1] + O[mt][ntv][3] * li1;
        }
    }
}

extern "C" void kernel_launch(void* const* d_in, const int* in_sizes, int n_in,
                              void* d_out, int out_size) {
    const float* x = (const float*)d_in[0];
    float* out = (float*)d_out;
    (void)in_sizes; (void)n_in; (void)out_size;

    cudaFuncSetAttribute(convert_kernel,
                         cudaFuncAttributeMaxDynamicSharedMemorySize, CONV_SMEM);
    cudaFuncSetAttribute(attn_hmma_kernel,
                         cudaFuncAttributeMaxDynamicSharedMemorySize, MAIN_SMEM);

    convert_kernel<<<Bq * 32, 256, CONV_SMEM>>>(x);
    attn_hmma_kernel<<<Bq * 16, NT, MAIN_SMEM>>>(x, out);
}